// round 1
// baseline (speedup 1.0000x reference)
#include <cuda_runtime.h>

#define BB 4
#define CC 64
#define NN 4096
#define TN 64

// scratch (allocation-free rule: __device__ globals)
__device__ float g_a[BB * NN];
__device__ float g_d[BB * NN];
__device__ float g_u[BB * CC];
__device__ float g_v[BB * CC];
__device__ float g_W0t[CC * CC];   // W0^T : [c][o]
__device__ float g_W1t[CC * CC];   // W1^T : [c][o]
__device__ float g_scale[CC];
__device__ float g_shift[CC];

// ---------------------------------------------------------------------------
// K1: blocks 0..3 -> per-batch a = relu(tanh(w)), S = sum(a), d = rsqrt(a*S+1)
//     block 4     -> transpose conv_w into c-major W0t/W1t, fold BN into scale/shift
// ---------------------------------------------------------------------------
__global__ void k_prep(const float* __restrict__ w,
                       const float* __restrict__ conv_w,
                       const float* __restrict__ conv_b,
                       const float* __restrict__ gamma,
                       const float* __restrict__ beta,
                       const float* __restrict__ mean,
                       const float* __restrict__ var) {
    __shared__ float red[32];
    __shared__ float S_sh;
    const int tid = threadIdx.x;   // 1024
    const int blk = blockIdx.x;

    if (blk < BB) {
        const int b = blk;
        float4 wv = ((const float4*)(w + b * NN))[tid];
        float a0 = fmaxf(tanhf(wv.x), 0.f);
        float a1 = fmaxf(tanhf(wv.y), 0.f);
        float a2 = fmaxf(tanhf(wv.z), 0.f);
        float a3 = fmaxf(tanhf(wv.w), 0.f);
        ((float4*)(g_a + b * NN))[tid] = make_float4(a0, a1, a2, a3);

        float s = a0 + a1 + a2 + a3;
        #pragma unroll
        for (int off = 16; off; off >>= 1) s += __shfl_down_sync(0xffffffffu, s, off);
        if ((tid & 31) == 0) red[tid >> 5] = s;
        __syncthreads();
        if (tid == 0) {
            float t = 0.f;
            #pragma unroll
            for (int i = 0; i < 32; i++) t += red[i];
            S_sh = t;
        }
        __syncthreads();
        const float S = S_sh;
        float4 dv;
        dv.x = rsqrtf(fmaf(a0, S, 1.f));
        dv.y = rsqrtf(fmaf(a1, S, 1.f));
        dv.z = rsqrtf(fmaf(a2, S, 1.f));
        dv.w = rsqrtf(fmaf(a3, S, 1.f));
        ((float4*)(g_d + b * NN))[tid] = dv;
    } else {
        // transpose conv_w [64][128] -> W0t/W1t [c][o]
        for (int idx = tid; idx < CC * 2 * CC; idx += 1024) {
            int o = idx >> 7;        // /128
            int k = idx & 127;
            float val = conv_w[idx];
            if (k < CC) g_W0t[k * CC + o] = val;
            else        g_W1t[(k - CC) * CC + o] = val;
        }
        if (tid < CC) {
            float s = gamma[tid] * rsqrtf(var[tid] + 1e-5f);
            g_scale[tid] = s;
            g_shift[tid] = fmaf(conv_b[tid] - mean[tid], s, beta[tid]);
        }
    }
}

// ---------------------------------------------------------------------------
// K2: per (b,c) block: u = sum_n x*a ; v = sum_n x*a*d
// ---------------------------------------------------------------------------
__global__ void k_uv(const float* __restrict__ x) {
    const int c = blockIdx.x;
    const int b = blockIdx.y;
    const int tid = threadIdx.x;   // 256
    const float4* x4 = (const float4*)(x + (size_t)(b * CC + c) * NN);
    const float4* a4 = (const float4*)(g_a + b * NN);
    const float4* d4 = (const float4*)(g_d + b * NN);

    float su = 0.f, sv = 0.f;
    #pragma unroll
    for (int k = 0; k < 4; k++) {
        int i = tid + k * 256;
        float4 xv = x4[i];
        float4 av = a4[i];
        float4 dv = d4[i];
        float t0 = xv.x * av.x, t1 = xv.y * av.y, t2 = xv.z * av.z, t3 = xv.w * av.w;
        su += t0 + t1 + t2 + t3;
        sv += t0 * dv.x + t1 * dv.y + t2 * dv.z + t3 * dv.w;
    }
    __shared__ float redu[8], redv[8];
    #pragma unroll
    for (int off = 16; off; off >>= 1) {
        su += __shfl_down_sync(0xffffffffu, su, off);
        sv += __shfl_down_sync(0xffffffffu, sv, off);
    }
    if ((tid & 31) == 0) { redu[tid >> 5] = su; redv[tid >> 5] = sv; }
    __syncthreads();
    if (tid == 0) {
        float tu = 0.f, tv = 0.f;
        #pragma unroll
        for (int i = 0; i < 8; i++) { tu += redu[i]; tv += redv[i]; }
        g_u[b * CC + c] = tu;
        g_v[b * CC + c] = tv;
    }
}

// ---------------------------------------------------------------------------
// K3: main fused GEMM + rank-1 terms + BN + ReLU.
// Grid (N/TN, B), 256 threads. Warp w owns o in [8w,8w+8), lane owns 2 n.
// ---------------------------------------------------------------------------
__global__ void __launch_bounds__(256) k_main(const float* __restrict__ x,
                                              const float* __restrict__ conv_w,
                                              float* __restrict__ out) {
    const int b  = blockIdx.y;
    const int n0 = blockIdx.x * TN;
    const int tid = threadIdx.x;

    __shared__ float xs[CC][TN];        // 16 KB
    __shared__ float p_s[CC], q_s[CC];

    // stage x tile: 64 rows x 64 floats
    {
        const float4* xg = (const float4*)(x + (size_t)b * CC * NN + n0);
        #pragma unroll
        for (int k = 0; k < 4; k++) {
            int f = tid + k * 256;          // 0..1023 float4 slots (64 x 16)
            int c = f >> 4, j = f & 15;
            ((float4*)xs)[c * (TN / 4) + j] = xg[c * (NN / 4) + j];
        }
    }

    // p[o] = W0[o,:].u ; q[o] = W1[o,:].v  (conv_w rows are contiguous)
    if (tid < 128) {
        const int o = tid & 63;
        const bool isq = tid >= 64;
        const float4* Wr = (const float4*)(conv_w + o * 128 + (isq ? 64 : 0));
        const float4* uv = (const float4*)((isq ? g_v : g_u) + b * CC);
        float s = 0.f;
        #pragma unroll
        for (int c4 = 0; c4 < 16; c4++) {
            float4 wv = __ldg(Wr + c4);
            float4 u  = __ldg(uv + c4);
            s += wv.x * u.x + wv.y * u.y + wv.z * u.z + wv.w * u.w;
        }
        if (isq) q_s[o] = s; else p_s[o] = s;
    }
    __syncthreads();

    const int warp = tid >> 5, lane = tid & 31;
    const int ow = warp << 3;           // o base
    const int nl = lane << 1;           // n within tile
    const int n = n0 + nl;

    const float2 a2 = *(const float2*)(g_a + b * NN + n);
    const float2 dv = *(const float2*)(g_d + b * NN + n);
    const float dd0 = dv.x * dv.x, dd1 = dv.y * dv.y;
    const float da0 = dv.x * a2.x, da1 = dv.y * a2.y;

    float acc[8][2];
    #pragma unroll
    for (int i = 0; i < 8; i++) { acc[i][0] = 0.f; acc[i][1] = 0.f; }

    #pragma unroll 4
    for (int c = 0; c < CC; c++) {
        float2 xv = *(const float2*)&xs[c][nl];
        float xd0 = xv.x * dd0;
        float xd1 = xv.y * dd1;
        float4 w0a = __ldg((const float4*)(g_W0t + c * CC + ow));
        float4 w0b = __ldg((const float4*)(g_W0t + c * CC + ow + 4));
        float4 w1a = __ldg((const float4*)(g_W1t + c * CC + ow));
        float4 w1b = __ldg((const float4*)(g_W1t + c * CC + ow + 4));
        float w0v[8] = {w0a.x, w0a.y, w0a.z, w0a.w, w0b.x, w0b.y, w0b.z, w0b.w};
        float w1v[8] = {w1a.x, w1a.y, w1a.z, w1a.w, w1b.x, w1b.y, w1b.z, w1b.w};
        #pragma unroll
        for (int oi = 0; oi < 8; oi++) {
            acc[oi][0] = fmaf(w0v[oi], xv.x, acc[oi][0]);
            acc[oi][1] = fmaf(w0v[oi], xv.y, acc[oi][1]);
            acc[oi][0] = fmaf(w1v[oi], xd0, acc[oi][0]);
            acc[oi][1] = fmaf(w1v[oi], xd1, acc[oi][1]);
        }
    }

    #pragma unroll
    for (int oi = 0; oi < 8; oi++) {
        const int o = ow + oi;
        const float sc = __ldg(g_scale + o);
        const float sh = __ldg(g_shift + o);
        const float pp = p_s[o];
        const float qq = q_s[o];
        float y0 = fmaf(pp, a2.x, acc[oi][0]);
        float y1 = fmaf(pp, a2.y, acc[oi][1]);
        y0 = fmaf(qq, da0, y0);
        y1 = fmaf(qq, da1, y1);
        y0 = fmaxf(fmaf(y0, sc, sh), 0.f);
        y1 = fmaxf(fmaf(y1, sc, sh), 0.f);
        *(float2*)(out + (size_t)(b * CC + o) * NN + n) = make_float2(y0, y1);
    }
}

// ---------------------------------------------------------------------------
extern "C" void kernel_launch(void* const* d_in, const int* in_sizes, int n_in,
                              void* d_out, int out_size) {
    const float* x      = (const float*)d_in[0];
    const float* w      = (const float*)d_in[1];
    const float* conv_w = (const float*)d_in[2];
    const float* conv_b = (const float*)d_in[3];
    const float* gamma  = (const float*)d_in[4];
    const float* beta   = (const float*)d_in[5];
    const float* mean   = (const float*)d_in[6];
    const float* var    = (const float*)d_in[7];
    float* out = (float*)d_out;

    k_prep<<<BB + 1, 1024>>>(w, conv_w, conv_b, gamma, beta, mean, var);
    k_uv<<<dim3(CC, BB), 256>>>(x);
    k_main<<<dim3(NN / TN, BB), 256>>>(x, conv_w, out);
}

// round 2
// speedup vs baseline: 1.3399x; 1.3399x over previous
#include <cuda_runtime.h>

#define BB 4
#define CC 64
#define NN 4096
#define TN 128

typedef unsigned long long ull;

// scratch (allocation-free rule: __device__ globals)
__device__ float g_a[BB * NN];
__device__ float g_d[BB * NN];
__device__ float g_u[BB * CC];
__device__ float g_v[BB * CC];
__device__ float g_W0d[CC * 2 * CC];   // [c][o*2] duplicated {w,w}
__device__ float g_W1d[CC * 2 * CC];   // [c][o*2] duplicated {w,w}
__device__ float g_scale[CC];
__device__ float g_shift[CC];

// ---- f32x2 packed helpers (sm_100 PTX) ------------------------------------
__device__ __forceinline__ ull pack2(float lo, float hi) {
    ull r; asm("mov.b64 %0, {%1, %2};" : "=l"(r) : "f"(lo), "f"(hi)); return r;
}
__device__ __forceinline__ void unpack2(ull v, float& lo, float& hi) {
    asm("mov.b64 {%0, %1}, %2;" : "=f"(lo), "=f"(hi) : "l"(v));
}
__device__ __forceinline__ ull fma2(ull a, ull b, ull c) {
    ull d; asm("fma.rn.f32x2 %0, %1, %2, %3;" : "=l"(d) : "l"(a), "l"(b), "l"(c)); return d;
}
__device__ __forceinline__ ull mul2(ull a, ull b) {
    ull d; asm("mul.rn.f32x2 %0, %1, %2;" : "=l"(d) : "l"(a), "l"(b)); return d;
}

// relu(tanh(x)) without the tanhf libcall; exact for x<=0, ~1e-7 rel for x>0
__device__ __forceinline__ float relutanh(float x) {
    if (x <= 0.f) return 0.f;
    float e = __expf(-2.f * x);
    return (1.f - e) * __frcp_rn(1.f + e);
}

// ---------------------------------------------------------------------------
// K1: blocks 0..3 -> per-batch a = relu(tanh(w)), S = sum(a), d = rsqrt(a*S+1)
//     block 4     -> duplicate-transpose conv_w, fold BN into scale/shift
// ---------------------------------------------------------------------------
__global__ void __launch_bounds__(1024) k_prep(
        const float* __restrict__ w,
        const float* __restrict__ conv_w,
        const float* __restrict__ conv_b,
        const float* __restrict__ gamma,
        const float* __restrict__ beta,
        const float* __restrict__ mean,
        const float* __restrict__ var) {
    __shared__ float red[32];
    __shared__ float S_sh;
    const int tid = threadIdx.x;
    const int blk = blockIdx.x;

    if (blk < BB) {
        const int b = blk;
        float4 wv = ((const float4*)(w + b * NN))[tid];
        float a0 = relutanh(wv.x);
        float a1 = relutanh(wv.y);
        float a2 = relutanh(wv.z);
        float a3 = relutanh(wv.w);
        ((float4*)(g_a + b * NN))[tid] = make_float4(a0, a1, a2, a3);

        float s = a0 + a1 + a2 + a3;
        #pragma unroll
        for (int off = 16; off; off >>= 1) s += __shfl_down_sync(0xffffffffu, s, off);
        if ((tid & 31) == 0) red[tid >> 5] = s;
        __syncthreads();
        if (tid == 0) {
            float t = 0.f;
            #pragma unroll
            for (int i = 0; i < 32; i++) t += red[i];
            S_sh = t;
        }
        __syncthreads();
        const float S = S_sh;
        float4 dv;
        dv.x = rsqrtf(fmaf(a0, S, 1.f));
        dv.y = rsqrtf(fmaf(a1, S, 1.f));
        dv.z = rsqrtf(fmaf(a2, S, 1.f));
        dv.w = rsqrtf(fmaf(a3, S, 1.f));
        ((float4*)(g_d + b * NN))[tid] = dv;
    } else {
        // conv_w [o][k], k in [0,128) -> duplicated c-major [c][2o]{w,w}
        for (int idx = tid; idx < CC * 2 * CC; idx += 1024) {
            int o = idx >> 7;
            int k = idx & 127;
            float val = conv_w[idx];
            float* dst = (k < CC) ? (g_W0d + k * 2 * CC + o * 2)
                                  : (g_W1d + (k - CC) * 2 * CC + o * 2);
            dst[0] = val; dst[1] = val;
        }
        if (tid < CC) {
            float s = gamma[tid] * rsqrtf(var[tid] + 1e-5f);
            g_scale[tid] = s;
            g_shift[tid] = fmaf(conv_b[tid] - mean[tid], s, beta[tid]);
        }
    }
}

// ---------------------------------------------------------------------------
// K2: per (b,c): u = sum_n x*a ; v = sum_n x*a*d
// ---------------------------------------------------------------------------
__global__ void __launch_bounds__(256) k_uv(const float* __restrict__ x) {
    const int c = blockIdx.x;
    const int b = blockIdx.y;
    const int tid = threadIdx.x;
    const float4* x4 = (const float4*)(x + (size_t)(b * CC + c) * NN);
    const float4* a4 = (const float4*)(g_a + b * NN);
    const float4* d4 = (const float4*)(g_d + b * NN);

    float su = 0.f, sv = 0.f;
    #pragma unroll
    for (int k = 0; k < 4; k++) {
        int i = tid + k * 256;
        float4 xv = x4[i];
        float4 av = a4[i];
        float4 dv = d4[i];
        float t0 = xv.x * av.x, t1 = xv.y * av.y, t2 = xv.z * av.z, t3 = xv.w * av.w;
        su += t0 + t1 + t2 + t3;
        sv += t0 * dv.x + t1 * dv.y + t2 * dv.z + t3 * dv.w;
    }
    __shared__ float redu[8], redv[8];
    #pragma unroll
    for (int off = 16; off; off >>= 1) {
        su += __shfl_down_sync(0xffffffffu, su, off);
        sv += __shfl_down_sync(0xffffffffu, sv, off);
    }
    if ((tid & 31) == 0) { redu[tid >> 5] = su; redv[tid >> 5] = sv; }
    __syncthreads();
    if (tid == 0) {
        float tu = 0.f, tv = 0.f;
        #pragma unroll
        for (int i = 0; i < 8; i++) { tu += redu[i]; tv += redv[i]; }
        g_u[b * CC + c] = tu;
        g_v[b * CC + c] = tv;
    }
}

// ---------------------------------------------------------------------------
// K3: fused GEMM + rank-1 + BN + ReLU, f32x2 packed math.
// Grid (NN/TN=32, BB) = 128 blocks, 256 threads.
// Warp w owns o in [8w, 8w+8); lane owns 4 n (two f32x2 pairs).
// Dynamic SMEM: xs[64][128] | w0s[64][128] | w1s[64][128]  = 96 KB.
// ---------------------------------------------------------------------------
__global__ void __launch_bounds__(256) k_main(const float* __restrict__ x,
                                              const float* __restrict__ conv_w,
                                              float* __restrict__ out) {
    extern __shared__ float sm[];
    float* xs  = sm;                 // [c][n]  64*128
    float* w0s = sm + CC * TN;       // [c][2o] duplicated
    float* w1s = sm + 2 * CC * TN;
    __shared__ float p_s[CC], q_s[CC];

    const int b  = blockIdx.y;
    const int n0 = blockIdx.x * TN;
    const int tid = threadIdx.x;

    // stage x tile (64 rows x 128 cols) + duplicated weights (flat copies)
    {
        const float* xb = x + (size_t)b * CC * NN + n0;
        float4* xs4  = (float4*)xs;
        float4* w0s4 = (float4*)w0s;
        float4* w1s4 = (float4*)w1s;
        const float4* gw0 = (const float4*)g_W0d;
        const float4* gw1 = (const float4*)g_W1d;
        #pragma unroll
        for (int k = 0; k < 8; k++) {
            int i = tid + k * 256;            // 0..2047 float4 slots
            int c = i >> 5, j = i & 31;       // 32 float4 per row
            xs4[i]  = ((const float4*)(xb + c * NN))[j];
            w0s4[i] = gw0[i];
            w1s4[i] = gw1[i];
        }
    }

    // p[o] = W0[o,:].u ; q[o] = W1[o,:].v
    if (tid < 128) {
        const int o = tid & 63;
        const bool isq = tid >= 64;
        const float4* Wr = (const float4*)(conv_w + o * 128 + (isq ? CC : 0));
        const float4* uv = (const float4*)((isq ? g_v : g_u) + b * CC);
        float s = 0.f;
        #pragma unroll
        for (int c4 = 0; c4 < 16; c4++) {
            float4 wv = __ldg(Wr + c4);
            float4 u  = __ldg(uv + c4);
            s += wv.x * u.x + wv.y * u.y + wv.z * u.z + wv.w * u.w;
        }
        if (isq) q_s[o] = s; else p_s[o] = s;
    }
    __syncthreads();

    const int warp = tid >> 5, lane = tid & 31;
    const int ow = warp << 3;            // o base
    const int nl = lane << 2;            // n within tile (4 per lane)
    const int n  = n0 + nl;

    const float4 av  = *(const float4*)(g_a + b * NN + n);
    const float4 dvv = *(const float4*)(g_d + b * NN + n);
    const ull dd01 = pack2(dvv.x * dvv.x, dvv.y * dvv.y);
    const ull dd23 = pack2(dvv.z * dvv.z, dvv.w * dvv.w);

    ull acc[8][2];
    #pragma unroll
    for (int i = 0; i < 8; i++) { acc[i][0] = 0ull; acc[i][1] = 0ull; }

    const float* xrow = xs + nl;
    const float* w0row = w0s + (ow << 1);
    const float* w1row = w1s + (ow << 1);

    #pragma unroll 4
    for (int c = 0; c < CC; c++) {
        ull x01 = *(const ull*)(xrow + c * TN);
        ull x23 = *(const ull*)(xrow + c * TN + 2);
        ull xd01 = mul2(x01, dd01);
        ull xd23 = mul2(x23, dd23);
        const ull* w0p = (const ull*)(w0row + c * 2 * CC);
        const ull* w1p = (const ull*)(w1row + c * 2 * CC);
        #pragma unroll
        for (int oi = 0; oi < 8; oi++) {
            ull w0 = w0p[oi];
            ull w1 = w1p[oi];
            acc[oi][0] = fma2(w0, x01, acc[oi][0]);
            acc[oi][1] = fma2(w0, x23, acc[oi][1]);
            acc[oi][0] = fma2(w1, xd01, acc[oi][0]);
            acc[oi][1] = fma2(w1, xd23, acc[oi][1]);
        }
    }

    const float da0 = dvv.x * av.x, da1 = dvv.y * av.y;
    const float da2 = dvv.z * av.z, da3 = dvv.w * av.w;

    #pragma unroll
    for (int oi = 0; oi < 8; oi++) {
        const int o = ow + oi;
        const float sc = g_scale[o];
        const float sh = g_shift[o];
        const float pp = p_s[o];
        const float qq = q_s[o];
        float y0, y1, y2, y3;
        unpack2(acc[oi][0], y0, y1);
        unpack2(acc[oi][1], y2, y3);
        y0 = fmaf(qq, da0, fmaf(pp, av.x, y0));
        y1 = fmaf(qq, da1, fmaf(pp, av.y, y1));
        y2 = fmaf(qq, da2, fmaf(pp, av.z, y2));
        y3 = fmaf(qq, da3, fmaf(pp, av.w, y3));
        y0 = fmaxf(fmaf(y0, sc, sh), 0.f);
        y1 = fmaxf(fmaf(y1, sc, sh), 0.f);
        y2 = fmaxf(fmaf(y2, sc, sh), 0.f);
        y3 = fmaxf(fmaf(y3, sc, sh), 0.f);
        *(float4*)(out + (size_t)(b * CC + o) * NN + n) = make_float4(y0, y1, y2, y3);
    }
}

// ---------------------------------------------------------------------------
extern "C" void kernel_launch(void* const* d_in, const int* in_sizes, int n_in,
                              void* d_out, int out_size) {
    const float* x      = (const float*)d_in[0];
    const float* w      = (const float*)d_in[1];
    const float* conv_w = (const float*)d_in[2];
    const float* conv_b = (const float*)d_in[3];
    const float* gamma  = (const float*)d_in[4];
    const float* beta   = (const float*)d_in[5];
    const float* mean   = (const float*)d_in[6];
    const float* var    = (const float*)d_in[7];
    float* out = (float*)d_out;

    const int smem = 3 * CC * TN * sizeof(float);   // 96 KB
    cudaFuncSetAttribute(k_main, cudaFuncAttributeMaxDynamicSharedMemorySize, smem);

    k_prep<<<BB + 1, 1024>>>(w, conv_w, conv_b, gamma, beta, mean, var);
    k_uv<<<dim3(CC, BB), 256>>>(x);
    k_main<<<dim3(NN / TN, BB), 256, smem>>>(x, conv_w, out);
}

// round 3
// speedup vs baseline: 1.4414x; 1.0757x over previous
#include <cuda_runtime.h>

#define BB 4
#define CC 64
#define NN 4096
#define TN 128

typedef unsigned long long ull;

// scratch (allocation-free rule: __device__ globals)
__device__ float g_a[BB * NN];
__device__ float g_d[BB * NN];
__device__ float g_u[BB * CC];
__device__ float g_v[BB * CC];
__device__ float g_W0d[CC * 2 * CC];   // [c][o*2] duplicated {w,w}
__device__ float g_W1d[CC * 2 * CC];   // [c][o*2] duplicated {w,w}
__device__ float g_scale[CC];
__device__ float g_shift[CC];

// ---- f32x2 packed helpers (sm_100 PTX) ------------------------------------
__device__ __forceinline__ ull pack2(float lo, float hi) {
    ull r; asm("mov.b64 %0, {%1, %2};" : "=l"(r) : "f"(lo), "f"(hi)); return r;
}
__device__ __forceinline__ void unpack2(ull v, float& lo, float& hi) {
    asm("mov.b64 {%0, %1}, %2;" : "=f"(lo), "=f"(hi) : "l"(v));
}
__device__ __forceinline__ ull fma2(ull a, ull b, ull c) {
    ull d; asm("fma.rn.f32x2 %0, %1, %2, %3;" : "=l"(d) : "l"(a), "l"(b), "l"(c)); return d;
}
__device__ __forceinline__ ull mul2(ull a, ull b) {
    ull d; asm("mul.rn.f32x2 %0, %1, %2;" : "=l"(d) : "l"(a), "l"(b)); return d;
}

// relu(tanh(x)) without the tanhf libcall; exact for x<=0, ~1e-7 rel for x>0
__device__ __forceinline__ float relutanh(float x) {
    if (x <= 0.f) return 0.f;
    float e = __expf(-2.f * x);
    return (1.f - e) * __frcp_rn(1.f + e);
}

// ---------------------------------------------------------------------------
// K1 (fused prep + uv): grid (CC+1, BB), 256 threads.
//  blocks (c<CC, b): redundantly compute a,d (regs), S; block c==0 writes
//                    g_a/g_d; all compute u,v for channel c of batch b.
//  block (CC, 0):    duplicate-transpose conv_w, fold BN into scale/shift.
// ---------------------------------------------------------------------------
__global__ void __launch_bounds__(256) k_uv(
        const float* __restrict__ x,
        const float* __restrict__ w,
        const float* __restrict__ conv_w,
        const float* __restrict__ conv_b,
        const float* __restrict__ gamma,
        const float* __restrict__ beta,
        const float* __restrict__ mean,
        const float* __restrict__ var) {
    const int c = blockIdx.x;
    const int b = blockIdx.y;
    const int tid = threadIdx.x;

    if (c == CC) {
        if (b != 0) return;
        // conv_w [o][k] -> duplicated c-major [c][2o]{w,w}
        for (int idx = tid; idx < CC * 2 * CC; idx += 256) {
            int o = idx >> 7;
            int k = idx & 127;
            float val = conv_w[idx];
            float* dst = (k < CC) ? (g_W0d + k * 2 * CC + o * 2)
                                  : (g_W1d + (k - CC) * 2 * CC + o * 2);
            dst[0] = val; dst[1] = val;
        }
        if (tid < CC) {
            float s = gamma[tid] * rsqrtf(var[tid] + 1e-5f);
            g_scale[tid] = s;
            g_shift[tid] = fmaf(conv_b[tid] - mean[tid], s, beta[tid]);
        }
        return;
    }

    __shared__ float red[8], red2[8];
    __shared__ float S_sh;

    // a for all N (16 values/thread), accumulate S
    const float4* w4 = (const float4*)(w + b * NN);
    float av[16];
    float s = 0.f;
    #pragma unroll
    for (int k = 0; k < 4; k++) {
        float4 wv = w4[tid + k * 256];
        av[k * 4 + 0] = relutanh(wv.x);
        av[k * 4 + 1] = relutanh(wv.y);
        av[k * 4 + 2] = relutanh(wv.z);
        av[k * 4 + 3] = relutanh(wv.w);
        s += av[k * 4 + 0] + av[k * 4 + 1] + av[k * 4 + 2] + av[k * 4 + 3];
    }
    #pragma unroll
    for (int off = 16; off; off >>= 1) s += __shfl_down_sync(0xffffffffu, s, off);
    if ((tid & 31) == 0) red[tid >> 5] = s;
    __syncthreads();
    if (tid == 0) {
        float t = 0.f;
        #pragma unroll
        for (int i = 0; i < 8; i++) t += red[i];
        S_sh = t;
    }
    __syncthreads();
    const float S = S_sh;

    float dv[16];
    #pragma unroll
    for (int i = 0; i < 16; i++) dv[i] = rsqrtf(fmaf(av[i], S, 1.f));

    if (c == 0) {
        #pragma unroll
        for (int k = 0; k < 4; k++) {
            ((float4*)(g_a + b * NN))[tid + k * 256] =
                make_float4(av[k*4+0], av[k*4+1], av[k*4+2], av[k*4+3]);
            ((float4*)(g_d + b * NN))[tid + k * 256] =
                make_float4(dv[k*4+0], dv[k*4+1], dv[k*4+2], dv[k*4+3]);
        }
    }

    // u = sum x*a ; v = sum x*a*d for channel c
    const float4* x4 = (const float4*)(x + (size_t)(b * CC + c) * NN);
    float su = 0.f, sv = 0.f;
    #pragma unroll
    for (int k = 0; k < 4; k++) {
        float4 xv = x4[tid + k * 256];
        float t0 = xv.x * av[k*4+0], t1 = xv.y * av[k*4+1];
        float t2 = xv.z * av[k*4+2], t3 = xv.w * av[k*4+3];
        su += t0 + t1 + t2 + t3;
        sv += t0 * dv[k*4+0] + t1 * dv[k*4+1] + t2 * dv[k*4+2] + t3 * dv[k*4+3];
    }
    __syncthreads();
    #pragma unroll
    for (int off = 16; off; off >>= 1) {
        su += __shfl_down_sync(0xffffffffu, su, off);
        sv += __shfl_down_sync(0xffffffffu, sv, off);
    }
    if ((tid & 31) == 0) { red[tid >> 5] = su; red2[tid >> 5] = sv; }
    __syncthreads();
    if (tid == 0) {
        float tu = 0.f, tv = 0.f;
        #pragma unroll
        for (int i = 0; i < 8; i++) { tu += red[i]; tv += red2[i]; }
        g_u[b * CC + c] = tu;
        g_v[b * CC + c] = tv;
    }
}

// ---------------------------------------------------------------------------
// K2: fused GEMM + rank-1 + BN + ReLU, f32x2 packed math, LDS.128 operands.
// Grid (NN/TN=32, BB) = 128 blocks, 256 threads.
// Warp w owns o in [8w, 8w+8); lane owns 4 n (two f32x2 pairs).
// Dynamic SMEM: xs[64][128] | w0s[64][128] | w1s[64][128] = 96 KB.
// ---------------------------------------------------------------------------
__global__ void __launch_bounds__(256) k_main(const float* __restrict__ x,
                                              const float* __restrict__ conv_w,
                                              float* __restrict__ out) {
    extern __shared__ float sm[];
    float* xs  = sm;                 // [c][n]
    float* w0s = sm + CC * TN;       // [c][2o] duplicated
    float* w1s = sm + 2 * CC * TN;
    __shared__ float p_s[CC], q_s[CC];

    const int b  = blockIdx.y;
    const int n0 = blockIdx.x * TN;
    const int tid = threadIdx.x;

    {
        const float* xb = x + (size_t)b * CC * NN + n0;
        float4* xs4  = (float4*)xs;
        float4* w0s4 = (float4*)w0s;
        float4* w1s4 = (float4*)w1s;
        const float4* gw0 = (const float4*)g_W0d;
        const float4* gw1 = (const float4*)g_W1d;
        #pragma unroll
        for (int k = 0; k < 8; k++) {
            int i = tid + k * 256;
            int c = i >> 5, j = i & 31;
            xs4[i]  = ((const float4*)(xb + c * NN))[j];
            w0s4[i] = gw0[i];
            w1s4[i] = gw1[i];
        }
    }

    // p[o] = W0[o,:].u ; q[o] = W1[o,:].v
    if (tid < 128) {
        const int o = tid & 63;
        const bool isq = tid >= 64;
        const float4* Wr = (const float4*)(conv_w + o * 128 + (isq ? CC : 0));
        const float4* uv = (const float4*)((isq ? g_v : g_u) + b * CC);
        float s = 0.f;
        #pragma unroll
        for (int c4 = 0; c4 < 16; c4++) {
            float4 wv = __ldg(Wr + c4);
            float4 u  = __ldg(uv + c4);
            s += wv.x * u.x + wv.y * u.y + wv.z * u.z + wv.w * u.w;
        }
        if (isq) q_s[o] = s; else p_s[o] = s;
    }
    __syncthreads();

    const int warp = tid >> 5, lane = tid & 31;
    const int ow = warp << 3;            // o base
    const int nl = lane << 2;            // n within tile
    const int n  = n0 + nl;

    const float4 av  = *(const float4*)(g_a + b * NN + n);
    const float4 dvv = *(const float4*)(g_d + b * NN + n);
    const ull dd01 = pack2(dvv.x * dvv.x, dvv.y * dvv.y);
    const ull dd23 = pack2(dvv.z * dvv.z, dvv.w * dvv.w);

    ull acc[8][2];
    #pragma unroll
    for (int i = 0; i < 8; i++) { acc[i][0] = 0ull; acc[i][1] = 0ull; }

    const float* xrow  = xs  + nl;
    const float* w0row = w0s + (ow << 1);
    const float* w1row = w1s + (ow << 1);

    #pragma unroll 4
    for (int c = 0; c < CC; c++) {
        ulonglong2 xv = *(const ulonglong2*)(xrow + c * TN);       // x01, x23
        ull xd01 = mul2(xv.x, dd01);
        ull xd23 = mul2(xv.y, dd23);
        const ulonglong2* w0p = (const ulonglong2*)(w0row + c * 2 * CC);
        const ulonglong2* w1p = (const ulonglong2*)(w1row + c * 2 * CC);
        #pragma unroll
        for (int g = 0; g < 4; g++) {                    // pairs of o
            ulonglong2 w0 = w0p[g];
            ulonglong2 w1 = w1p[g];
            const int o0 = g * 2, o1 = g * 2 + 1;
            acc[o0][0] = fma2(w0.x, xv.x, acc[o0][0]);
            acc[o0][1] = fma2(w0.x, xv.y, acc[o0][1]);
            acc[o1][0] = fma2(w0.y, xv.x, acc[o1][0]);
            acc[o1][1] = fma2(w0.y, xv.y, acc[o1][1]);
            acc[o0][0] = fma2(w1.x, xd01, acc[o0][0]);
            acc[o0][1] = fma2(w1.x, xd23, acc[o0][1]);
            acc[o1][0] = fma2(w1.y, xd01, acc[o1][0]);
            acc[o1][1] = fma2(w1.y, xd23, acc[o1][1]);
        }
    }

    const float da0 = dvv.x * av.x, da1 = dvv.y * av.y;
    const float da2 = dvv.z * av.z, da3 = dvv.w * av.w;

    #pragma unroll
    for (int oi = 0; oi < 8; oi++) {
        const int o = ow + oi;
        const float sc = g_scale[o];
        const float sh = g_shift[o];
        const float pp = p_s[o];
        const float qq = q_s[o];
        float y0, y1, y2, y3;
        unpack2(acc[oi][0], y0, y1);
        unpack2(acc[oi][1], y2, y3);
        y0 = fmaf(qq, da0, fmaf(pp, av.x, y0));
        y1 = fmaf(qq, da1, fmaf(pp, av.y, y1));
        y2 = fmaf(qq, da2, fmaf(pp, av.z, y2));
        y3 = fmaf(qq, da3, fmaf(pp, av.w, y3));
        y0 = fmaxf(fmaf(y0, sc, sh), 0.f);
        y1 = fmaxf(fmaf(y1, sc, sh), 0.f);
        y2 = fmaxf(fmaf(y2, sc, sh), 0.f);
        y3 = fmaxf(fmaf(y3, sc, sh), 0.f);
        *(float4*)(out + (size_t)(b * CC + o) * NN + n) = make_float4(y0, y1, y2, y3);
    }
}

// ---------------------------------------------------------------------------
extern "C" void kernel_launch(void* const* d_in, const int* in_sizes, int n_in,
                              void* d_out, int out_size) {
    const float* x      = (const float*)d_in[0];
    const float* w      = (const float*)d_in[1];
    const float* conv_w = (const float*)d_in[2];
    const float* conv_b = (const float*)d_in[3];
    const float* gamma  = (const float*)d_in[4];
    const float* beta   = (const float*)d_in[5];
    const float* mean   = (const float*)d_in[6];
    const float* var    = (const float*)d_in[7];
    float* out = (float*)d_out;

    const int smem = 3 * CC * TN * sizeof(float);   // 96 KB
    cudaFuncSetAttribute(k_main, cudaFuncAttributeMaxDynamicSharedMemorySize, smem);

    k_uv<<<dim3(CC + 1, BB), 256>>>(x, w, conv_w, conv_b, gamma, beta, mean, var);
    k_main<<<dim3(NN / TN, BB), 256, smem>>>(x, conv_w, out);
}

// round 4
// speedup vs baseline: 1.9091x; 1.3245x over previous
#include <cuda_runtime.h>

#define BB 4
#define CC 64
#define NN 4096
#define TN 64
#define GRID 256

typedef unsigned long long ull;

// scratch (allocation-free rule: __device__ globals, zero-initialized)
__device__ float g_a[BB * NN];
__device__ float g_d[BB * NN];
__device__ float g_u[BB * CC];
__device__ float g_v[BB * CC];
__device__ float g_W0t[CC * CC];     // [c][o]
__device__ float g_W1t[CC * CC];     // [c][o]
__device__ float g_scale[CC];
__device__ float g_shift[CC];
__device__ unsigned g_bar;           // monotonic barrier counter

// ---- f32x2 packed helpers ---------------------------------------------------
__device__ __forceinline__ ull pack2(float lo, float hi) {
    ull r; asm("mov.b64 %0, {%1, %2};" : "=l"(r) : "f"(lo), "f"(hi)); return r;
}
__device__ __forceinline__ void unpack2(ull v, float& lo, float& hi) {
    asm("mov.b64 {%0, %1}, %2;" : "=f"(lo), "=f"(hi) : "l"(v));
}
__device__ __forceinline__ ull fma2(ull a, ull b, ull c) {
    ull d; asm("fma.rn.f32x2 %0, %1, %2, %3;" : "=l"(d) : "l"(a), "l"(b), "l"(c)); return d;
}

__device__ __forceinline__ float relutanh(float x) {
    if (x <= 0.f) return 0.f;
    float e = __expf(-2.f * x);
    return (1.f - e) * __frcp_rn(1.f + e);
}

// -----------------------------------------------------------------------------
// Single fused kernel. grid=256 (1-D), 256 threads, 64KB dynamic smem.
// Phase 1: block (b = blk>>6, c = blk&63) computes a,d (regs) + u,v; c==0
//          writes g_a/g_d; b==0 blocks transpose conv_w row c; (0,0) does BN fold.
// Barrier: device-wide, monotonic atomic counter.
// Phase 2: block (b, ntile = blk&63): o-packed f32x2 GEMM + rank-1 + BN + ReLU.
// -----------------------------------------------------------------------------
__global__ void __launch_bounds__(256) k_fused(
        const float* __restrict__ x,
        const float* __restrict__ w,
        const float* __restrict__ conv_w,
        const float* __restrict__ conv_b,
        const float* __restrict__ gamma,
        const float* __restrict__ beta,
        const float* __restrict__ mean,
        const float* __restrict__ var,
        float* __restrict__ out) {
    extern __shared__ float sm[];
    float* xs  = sm;                  // [64][128] x duplicated {x,x}  32KB
    float* w0s = sm + CC * 2 * TN;    // [64][64]                     16KB
    float* w1s = w0s + CC * CC;       //                              16KB
    __shared__ float p_s[CC], q_s[CC], u_s[CC], v_s[CC];
    __shared__ float red[8], red2[8];
    __shared__ float S_sh;

    const int tid = threadIdx.x;
    const int blk = blockIdx.x;
    const int b = blk >> 6;
    const int c = blk & 63;

    // ================= Phase 1 =================
    const float4* w4 = (const float4*)(w + b * NN);
    float avr[16], dvr[16];
    {
        float s = 0.f;
        #pragma unroll
        for (int k = 0; k < 4; k++) {
            float4 wv = w4[tid + k * 256];
            avr[k*4+0] = relutanh(wv.x);
            avr[k*4+1] = relutanh(wv.y);
            avr[k*4+2] = relutanh(wv.z);
            avr[k*4+3] = relutanh(wv.w);
            s += avr[k*4+0] + avr[k*4+1] + avr[k*4+2] + avr[k*4+3];
        }
        #pragma unroll
        for (int off = 16; off; off >>= 1) s += __shfl_down_sync(0xffffffffu, s, off);
        if ((tid & 31) == 0) red[tid >> 5] = s;
        __syncthreads();
        if (tid == 0) {
            float t = 0.f;
            #pragma unroll
            for (int i = 0; i < 8; i++) t += red[i];
            S_sh = t;
        }
        __syncthreads();
        const float S = S_sh;
        #pragma unroll
        for (int i = 0; i < 16; i++) dvr[i] = rsqrtf(fmaf(avr[i], S, 1.f));
    }

    if (c == 0) {
        #pragma unroll
        for (int k = 0; k < 4; k++) {
            ((float4*)(g_a + b * NN))[tid + k * 256] =
                make_float4(avr[k*4+0], avr[k*4+1], avr[k*4+2], avr[k*4+3]);
            ((float4*)(g_d + b * NN))[tid + k * 256] =
                make_float4(dvr[k*4+0], dvr[k*4+1], dvr[k*4+2], dvr[k*4+3]);
        }
    }
    if (b == 0) {
        // transpose row c of both weight halves: W0t[c][o]=conv_w[o*128+c]
        if (tid < CC) {
            g_W0t[c * CC + tid] = conv_w[tid * 128 + c];
            g_W1t[c * CC + tid] = conv_w[tid * 128 + CC + c];
        }
        if (c == 0 && tid >= 64 && tid < 128) {
            int o = tid - 64;
            float s = gamma[o] * rsqrtf(var[o] + 1e-5f);
            g_scale[o] = s;
            g_shift[o] = fmaf(conv_b[o] - mean[o], s, beta[o]);
        }
    }

    // u = sum x*a ; v = sum x*a*d for channel (b,c)
    {
        const float4* x4 = (const float4*)(x + (size_t)(b * CC + c) * NN);
        float su = 0.f, sv = 0.f;
        #pragma unroll
        for (int k = 0; k < 4; k++) {
            float4 xv = x4[tid + k * 256];
            float t0 = xv.x * avr[k*4+0], t1 = xv.y * avr[k*4+1];
            float t2 = xv.z * avr[k*4+2], t3 = xv.w * avr[k*4+3];
            su += t0 + t1 + t2 + t3;
            sv += t0 * dvr[k*4+0] + t1 * dvr[k*4+1] + t2 * dvr[k*4+2] + t3 * dvr[k*4+3];
        }
        #pragma unroll
        for (int off = 16; off; off >>= 1) {
            su += __shfl_down_sync(0xffffffffu, su, off);
            sv += __shfl_down_sync(0xffffffffu, sv, off);
        }
        if ((tid & 31) == 0) { red[tid >> 5] = su; red2[tid >> 5] = sv; }
        __syncthreads();
        if (tid == 0) {
            float tu = 0.f, tv = 0.f;
            #pragma unroll
            for (int i = 0; i < 8; i++) { tu += red[i]; tv += red2[i]; }
            g_u[b * CC + c] = tu;
            g_v[b * CC + c] = tv;
        }
    }

    // ================= device-wide barrier =================
    __threadfence();
    __syncthreads();
    if (tid == 0) {
        unsigned old = atomicAdd(&g_bar, 1u);
        unsigned target = (old & ~255u) + 256u;   // GRID == 256
        unsigned vcur;
        do { vcur = *(volatile unsigned*)&g_bar; } while ((int)(vcur - target) < 0);
    }
    __syncthreads();

    // ================= Phase 2 =================
    const int n0 = c * TN;    // reuse c as n-tile index

    // stage x duplicated + weights
    {
        const float* xb = x + (size_t)(b * CC) * NN + n0;
        float4* xs4 = (float4*)xs;
        #pragma unroll
        for (int k = 0; k < 8; k++) {
            int i = tid + k * 256;          // 0..2047 = 64 rows x 32 float4
            int cc2 = i >> 5, j = i & 31;
            float2 xv = *(const float2*)(xb + cc2 * NN + j * 2);
            xs4[i] = make_float4(xv.x, xv.x, xv.y, xv.y);
        }
        float4* w0s4 = (float4*)w0s;
        float4* w1s4 = (float4*)w1s;
        const float4* gw0 = (const float4*)g_W0t;
        const float4* gw1 = (const float4*)g_W1t;
        #pragma unroll
        for (int k = 0; k < 4; k++) {
            int i = tid + k * 256;          // 1024 float4
            w0s4[i] = gw0[i];
            w1s4[i] = gw1[i];
        }
        if (tid < CC) {
            u_s[tid] = g_u[b * CC + tid];
            v_s[tid] = g_v[b * CC + tid];
        }
    }
    __syncthreads();

    // p[o] = sum_c W0t[c][o] u[c] ; q[o] = sum_c W1t[c][o] v[c]
    if (tid < 128) {
        const int o = tid & 63;
        const bool isq = tid >= 64;
        const float* W = isq ? w1s : w0s;
        const float* uv = isq ? v_s : u_s;
        float s = 0.f;
        #pragma unroll 8
        for (int cc2 = 0; cc2 < CC; cc2++) s = fmaf(W[cc2 * CC + o], uv[cc2], s);
        (isq ? q_s : p_s)[o] = s;
    }
    __syncthreads();

    const int warp = tid >> 5, lane = tid & 31;
    const int ow = warp << 3;           // 8 o per warp (4 o-pairs)
    const int nl = lane << 1;           // 2 n per lane

    ull acc0[4][2], acc1[4][2];
    #pragma unroll
    for (int i = 0; i < 4; i++) {
        acc0[i][0] = acc0[i][1] = 0ull;
        acc1[i][0] = acc1[i][1] = 0ull;
    }

    const float* xrow = xs + (lane << 2);   // dup pair start
    const float* w0p = w0s + ow;
    const float* w1p = w1s + ow;

    #pragma unroll 4
    for (int k = 0; k < CC; k++) {
        ulonglong2 xd  = *(const ulonglong2*)(xrow + k * 2 * TN);  // {x0,x0},{x1,x1}
        ulonglong2 wa0 = *(const ulonglong2*)(w0p + k * CC);       // o0..o3
        ulonglong2 wb0 = *(const ulonglong2*)(w0p + k * CC + 4);   // o4..o7
        ulonglong2 wa1 = *(const ulonglong2*)(w1p + k * CC);
        ulonglong2 wb1 = *(const ulonglong2*)(w1p + k * CC + 4);
        acc0[0][0] = fma2(wa0.x, xd.x, acc0[0][0]);
        acc0[0][1] = fma2(wa0.x, xd.y, acc0[0][1]);
        acc0[1][0] = fma2(wa0.y, xd.x, acc0[1][0]);
        acc0[1][1] = fma2(wa0.y, xd.y, acc0[1][1]);
        acc0[2][0] = fma2(wb0.x, xd.x, acc0[2][0]);
        acc0[2][1] = fma2(wb0.x, xd.y, acc0[2][1]);
        acc0[3][0] = fma2(wb0.y, xd.x, acc0[3][0]);
        acc0[3][1] = fma2(wb0.y, xd.y, acc0[3][1]);
        acc1[0][0] = fma2(wa1.x, xd.x, acc1[0][0]);
        acc1[0][1] = fma2(wa1.x, xd.y, acc1[0][1]);
        acc1[1][0] = fma2(wa1.y, xd.x, acc1[1][0]);
        acc1[1][1] = fma2(wa1.y, xd.y, acc1[1][1]);
        acc1[2][0] = fma2(wb1.x, xd.x, acc1[2][0]);
        acc1[2][1] = fma2(wb1.x, xd.y, acc1[2][1]);
        acc1[3][0] = fma2(wb1.y, xd.x, acc1[3][0]);
        acc1[3][1] = fma2(wb1.y, xd.y, acc1[3][1]);
    }

    // epilogue: y = acc0 + dd_n*acc1 + p*a_n + q*(d*a)_n ; BN ; ReLU
    const int ng = n0 + nl;
    const float2 a2 = *(const float2*)(g_a + b * NN + ng);
    const float2 d2 = *(const float2*)(g_d + b * NN + ng);
    const ull ddp0 = pack2(d2.x * d2.x, d2.x * d2.x);
    const ull ddp1 = pack2(d2.y * d2.y, d2.y * d2.y);
    const ull ap0  = pack2(a2.x, a2.x);
    const ull ap1  = pack2(a2.y, a2.y);
    const ull dap0 = pack2(d2.x * a2.x, d2.x * a2.x);
    const ull dap1 = pack2(d2.y * a2.y, d2.y * a2.y);

    #pragma unroll
    for (int op = 0; op < 4; op++) {
        const int o0 = ow + op * 2;
        ull pp = *(const ull*)(p_s + o0);
        ull qq = *(const ull*)(q_s + o0);
        ull sc = *(const ull*)(g_scale + o0);
        ull sh = *(const ull*)(g_shift + o0);
        ull y0 = fma2(acc1[op][0], ddp0, acc0[op][0]);
        y0 = fma2(pp, ap0, y0);
        y0 = fma2(qq, dap0, y0);
        y0 = fma2(y0, sc, sh);
        ull y1 = fma2(acc1[op][1], ddp1, acc0[op][1]);
        y1 = fma2(pp, ap1, y1);
        y1 = fma2(qq, dap1, y1);
        y1 = fma2(y1, sc, sh);
        float f00, f10, f01, f11;
        unpack2(y0, f00, f10);     // (o0,n0), (o1,n0)
        unpack2(y1, f01, f11);     // (o0,n1), (o1,n1)
        f00 = fmaxf(f00, 0.f); f01 = fmaxf(f01, 0.f);
        f10 = fmaxf(f10, 0.f); f11 = fmaxf(f11, 0.f);
        *(float2*)(out + (size_t)(b * CC + o0) * NN + ng)     = make_float2(f00, f01);
        *(float2*)(out + (size_t)(b * CC + o0 + 1) * NN + ng) = make_float2(f10, f11);
    }
}

// -----------------------------------------------------------------------------
extern "C" void kernel_launch(void* const* d_in, const int* in_sizes, int n_in,
                              void* d_out, int out_size) {
    const float* x      = (const float*)d_in[0];
    const float* w      = (const float*)d_in[1];
    const float* conv_w = (const float*)d_in[2];
    const float* conv_b = (const float*)d_in[3];
    const float* gamma  = (const float*)d_in[4];
    const float* beta   = (const float*)d_in[5];
    const float* mean   = (const float*)d_in[6];
    const float* var    = (const float*)d_in[7];
    float* out = (float*)d_out;

    const int smem = (CC * 2 * TN + 2 * CC * CC) * sizeof(float);  // 64 KB
    cudaFuncSetAttribute(k_fused, cudaFuncAttributeMaxDynamicSharedMemorySize, smem);

    k_fused<<<GRID, 256, smem>>>(x, w, conv_w, conv_b, gamma, beta, mean, var, out);
}